// round 14
// baseline (speedup 1.0000x reference)
#include <cuda_runtime.h>

#define NTRAJ  2048
#define TSTEPS 512
#define KDIM   (TSTEPS * 3)
#define PF     8
#define GROUPS (TSTEPS / PF)   // 64
#define DT     0.00833333333333333f

__device__ __forceinline__ float htanh(float x) {
    float y; asm("tanh.approx.f32 %0, %1;" : "=f"(y) : "f"(x)); return y;
}
// rcp.approx + 1 Newton step: <=1 ulp vs IEEE 1/x. Required: the reference's
// om = 1-K0 cancellation amplifies reciprocal error by P0/r (~4e4).
__device__ __forceinline__ float frcp_nr(float x) {
    float y; asm("rcp.approx.f32 %0, %1;" : "=f"(y) : "f"(x));
    float e = fmaf(-x, y, 1.0f);
    return fmaf(e, y, y);
}

// One scalar-observation 2x2 Kalman step — R6-exact arithmetic (rel 3.9e-7).
__device__ __forceinline__ void kstep(
    float& s0, float& s1, float& p00, float& p01, float& p11,
    float z, float c1, float c2, float c3, float c4,
    float q0, float q1, float r, float& S_out, float& M_out)
{
    float sp = fmaf(DT, s1, s0);
    float tv = htanh(100.0f * s1);
    float vp = fmaf(-c2, tv, c1 * s1);
    float a  = fmaf(c3, tv * tv, c4);

    float u   = fmaf(DT, p11, p01);
    float n00 = fmaf(DT, u, fmaf(DT, p01, p00)) + q0;
    float n01 = a * u;
    float n11 = fmaf(a * a, p11, q1);

    float S  = n00 + r;
    float is = frcp_nr(S);
    float yv = z - sp;
    float K0 = __fmul_rn(n00, is);
    float K1 = __fmul_rn(n01, is);
    s0 = fmaf(K0, yv, sp);
    s1 = fmaf(K1, yv, vp);
    float om = 1.0f - K0;
    p00 = om * n00;
    p01 = om * n01;
    p11 = fmaf(-K1, n01, n11);

    S_out = S;
    M_out = yv * (is * yv);
}

// Fused EKF + combine. Block = 96 threads = 3 warps; warp c runs component c
// of trajectories [blockIdx*32, blockIdx*32+32). Per 8-step group, (S,M) go
// to a double-buffered smem tile; the theta warp (lighter: a==1) combines the
// PREVIOUS group and writes losses. One __syncthreads per group.
__global__ void __launch_bounds__(96, 1) ekf_fused(
    const float* __restrict__ meas,
    const float* __restrict__ init_state,
    const float* __restrict__ dyna,
    const float* __restrict__ Q,
    const float* __restrict__ R,
    const float* __restrict__ P0,
    float* __restrict__ out)
{
    __shared__ float2 sm[2][3][PF][32];   // [buf][comp][t-in-group][traj]

    const int lane = threadIdx.x & 31;
    const int c    = threadIdx.x >> 5;    // warp id == component
    const int traj = blockIdx.x * 32 + lane;

    const bool lin = (c == 2);
    const float fric = lin ? 0.0f : __ldg(dyna + 0);
    const float damp = lin ? 0.0f : __ldg(dyna + 1);

    const float c1 = 1.0f - DT * damp;
    const float c2 = DT * fric;
    const float c3 = 100.0f * c2;
    const float c4 = c1 - c3;

    const int pc = lin ? 4 : c;
    const int vc = lin ? 5 : c + 2;

    const float q0 = __ldg(Q + pc * 7);
    const float q1 = __ldg(Q + vc * 7);
    const float r  = __ldg(R + c * 4);

    float s0 = init_state[traj * 6 + pc];
    float s1 = init_state[traj * 6 + vc];

    float p00 = __ldg(P0 + pc * 7);
    float p01 = __ldg(P0 + pc * 6 + vc);
    float p11 = __ldg(P0 + vc * 7);

    const float* zb = meas + traj * KDIM + c;   // z(t) at zb[3*t]
    float* o = out + traj * TSTEPS;

    float zr[PF];
    #pragma unroll
    for (int i = 0; i < PF; ++i) zr[i] = zb[3 * i];

    #pragma unroll 1
    for (int g = 0; g < GROUPS; ++g) {
        const int t0 = g * PF;

        // theta warp: combine previous group's partials (overlaps x/y compute)
        if (c == 2 && g > 0) {
            const int pb = (g - 1) & 1;
            float l[PF];
            #pragma unroll
            for (int u8 = 0; u8 < PF; ++u8) {
                float2 px = sm[pb][0][u8][lane];
                float2 py = sm[pb][1][u8][lane];
                float2 pt = sm[pb][2][u8][lane];
                l[u8] = fmaf(px.x * py.x, pt.x, (px.y + py.y) + pt.y);
            }
            float4* d = reinterpret_cast<float4*>(o + (g - 1) * PF);
            d[0] = make_float4(l[0], l[1], l[2], l[3]);
            d[1] = make_float4(l[4], l[5], l[6], l[7]);
        }

        #pragma unroll
        for (int u8 = 0; u8 < PF; ++u8) {
            float z = zr[u8];
            int tn = t0 + u8 + PF; tn = (tn > TSTEPS - 1) ? (TSTEPS - 1) : tn;
            zr[u8] = zb[3 * tn];
            float S, M;
            kstep(s0, s1, p00, p01, p11, z, c1, c2, c3, c4, q0, q1, r, S, M);
            sm[g & 1][c][u8][lane] = make_float2(S, M);
        }

        __syncthreads();
    }

    // final group's combine (buffer (GROUPS-1)&1 = 1)
    if (c == 2) {
        float l[PF];
        #pragma unroll
        for (int u8 = 0; u8 < PF; ++u8) {
            float2 px = sm[1][0][u8][lane];
            float2 py = sm[1][1][u8][lane];
            float2 pt = sm[1][2][u8][lane];
            l[u8] = fmaf(px.x * py.x, pt.x, (px.y + py.y) + pt.y);
        }
        float4* d = reinterpret_cast<float4*>(o + (GROUPS - 1) * PF);
        d[0] = make_float4(l[0], l[1], l[2], l[3]);
        d[1] = make_float4(l[4], l[5], l[6], l[7]);
    }
}

extern "C" void kernel_launch(void* const* d_in, const int* in_sizes, int n_in,
                              void* d_out, int out_size) {
    const float* meas = (const float*)d_in[0];
    const float* init = (const float*)d_in[1];
    const float* dyna = (const float*)d_in[2];
    const float* Q    = (const float*)d_in[3];
    const float* R    = (const float*)d_in[4];
    const float* P0   = (const float*)d_in[5];
    float* out = (float*)d_out;

    ekf_fused<<<NTRAJ / 32, 96>>>(meas, init, dyna, Q, R, P0, out);
}

// round 15
// speedup vs baseline: 1.2779x; 1.2779x over previous
#include <cuda_runtime.h>

#define NTRAJ  2048
#define TSTEPS 512
#define KDIM   (TSTEPS * 3)
#define NCH    (3 * NTRAJ)     // 6144 independent 2x2 Kalman chains
#define PF     8
#define DT     0.00833333333333333f

// Paired partials: g_part4[(t>>1)*NCH + chain] = (S_t, M_t, S_{t+1}, M_{t+1}).
// chain = c*NTRAJ + traj. 25 MB. Written with __stcs (evict-first) so the
// DRAM writeback drains during ekf (DRAM idle there) instead of stalling combine.
__device__ float4 g_part4[(TSTEPS / 2) * NCH];

__device__ __forceinline__ float htanh(float x) {
    float y; asm("tanh.approx.f32 %0, %1;" : "=f"(y) : "f"(x)); return y;
}
// rcp.approx + 1 Newton step: <=1 ulp vs IEEE 1/x. Required: the reference's
// om = 1-K0 cancellation amplifies reciprocal error by P0/r (~4e4).
__device__ __forceinline__ float frcp_nr(float x) {
    float y; asm("rcp.approx.f32 %0, %1;" : "=f"(y) : "f"(x));
    float e = fmaf(-x, y, 1.0f);
    return fmaf(e, y, y);
}

// One scalar-observation 2x2 Kalman step — R6-exact arithmetic (rel 3.9e-7).
__device__ __forceinline__ void kstep(
    float& s0, float& s1, float& p00, float& p01, float& p11,
    float z, float c1, float c2, float c3, float c4,
    float q0, float q1, float r, float& S_out, float& M_out)
{
    float sp = fmaf(DT, s1, s0);
    float tv = htanh(100.0f * s1);
    float vp = fmaf(-c2, tv, c1 * s1);
    float a  = fmaf(c3, tv * tv, c4);

    float u   = fmaf(DT, p11, p01);
    float n00 = fmaf(DT, u, fmaf(DT, p01, p00)) + q0;
    float n01 = a * u;
    float n11 = fmaf(a * a, p11, q1);

    float S  = n00 + r;
    float is = frcp_nr(S);
    float yv = z - sp;
    float K0 = __fmul_rn(n00, is);
    float K1 = __fmul_rn(n01, is);
    s0 = fmaf(K0, yv, sp);
    s1 = fmaf(K1, yv, vp);
    float om = 1.0f - K0;
    p00 = om * n00;
    p01 = om * n01;
    p11 = fmaf(-K1, n01, n11);

    S_out = S;
    M_out = yv * (is * yv);
}

// 6144 chains, one per lane (192 warps). z read directly from [traj][t][k]
// (12B/step stride -> ~90% L1 hits). Partials: one streaming STG.128 / 2 steps.
__global__ void __launch_bounds__(32, 1) ekf_k(
    const float* __restrict__ meas,
    const float* __restrict__ init_state,
    const float* __restrict__ dyna,
    const float* __restrict__ Q,
    const float* __restrict__ R,
    const float* __restrict__ P0)
{
    const int lane  = threadIdx.x & 31;
    const int chain = blockIdx.x * 32 + lane;
    const int c     = chain >> 11;          // 0,1,2
    const int traj  = chain & (NTRAJ - 1);

    const bool lin = (c == 2);
    const float fric = lin ? 0.0f : __ldg(dyna + 0);
    const float damp = lin ? 0.0f : __ldg(dyna + 1);

    const float c1 = 1.0f - DT * damp;
    const float c2 = DT * fric;
    const float c3 = 100.0f * c2;
    const float c4 = c1 - c3;

    const int pc = lin ? 4 : c;
    const int vc = lin ? 5 : c + 2;

    const float q0 = __ldg(Q + pc * 7);
    const float q1 = __ldg(Q + vc * 7);
    const float r  = __ldg(R + c * 4);

    float s0 = init_state[traj * 6 + pc];
    float s1 = init_state[traj * 6 + vc];

    float p00 = __ldg(P0 + pc * 7);
    float p01 = __ldg(P0 + pc * 6 + vc);
    float p11 = __ldg(P0 + vc * 7);

    const float* zb = meas + traj * KDIM + c;   // z(t) at zb[3*t]
    float4*      pp = g_part4 + chain;

    float zr[PF];
    #pragma unroll
    for (int i = 0; i < PF; ++i) zr[i] = zb[3 * i];

    const float* pz = zb + 3 * PF;

    float Sp, Mp;

    // main loop: 504 steps with unconditional prefetch (max step loaded = 511)
    #pragma unroll 1
    for (int t = 0; t < TSTEPS - PF; t += PF) {
        #pragma unroll
        for (int u8 = 0; u8 < PF; ++u8) {
            float z = zr[u8];
            zr[u8] = pz[3 * u8];
            float S, M;
            kstep(s0, s1, p00, p01, p11, z, c1, c2, c3, c4, q0, q1, r, S, M);
            if ((u8 & 1) == 0) { Sp = S; Mp = M; }
            else __stcs(pp + (u8 >> 1) * NCH, make_float4(Sp, Mp, S, M));
        }
        pz += 3 * PF;
        pp += (PF / 2) * NCH;
    }
    // tail: last 8 steps, no prefetch
    #pragma unroll
    for (int u8 = 0; u8 < PF; ++u8) {
        float S, M;
        kstep(s0, s1, p00, p01, p11, zr[u8], c1, c2, c3, c4, q0, q1, r, S, M);
        if ((u8 & 1) == 0) { Sp = S; Mp = M; }
        else __stcs(pp + (u8 >> 1) * NCH, make_float4(Sp, Mp, S, M));
    }
}

// loss[traj][t] = (Sx*Sy)*St + (mx+my)+mt from paired partials.
// Partials are dead after this read -> __ldcs (evict-first, no L2 pollution).
__global__ void combine_k(float* __restrict__ out) {
    __shared__ float tile[32][33];        // [t][traj]
    const int t0  = blockIdx.x * 32;
    const int tr0 = blockIdx.y * 32;
    const int tx = threadIdx.x, ty = threadIdx.y;   // ty in 0..15

    const float4* base = g_part4 + (t0 / 2 + ty) * NCH + tr0 + tx;
    float4 px = __ldcs(base);
    float4 py = __ldcs(base + NTRAJ);
    float4 pt = __ldcs(base + 2 * NTRAJ);
    tile[2 * ty][tx]     = fmaf(px.x * py.x, pt.x, (px.y + py.y) + pt.y);
    tile[2 * ty + 1][tx] = fmaf(px.z * py.z, pt.z, (px.w + py.w) + pt.w);
    __syncthreads();
    out[(tr0 + ty) * TSTEPS + t0 + tx]      = tile[tx][ty];
    out[(tr0 + ty + 16) * TSTEPS + t0 + tx] = tile[tx][ty + 16];
}

extern "C" void kernel_launch(void* const* d_in, const int* in_sizes, int n_in,
                              void* d_out, int out_size) {
    const float* meas = (const float*)d_in[0];
    const float* init = (const float*)d_in[1];
    const float* dyna = (const float*)d_in[2];
    const float* Q    = (const float*)d_in[3];
    const float* R    = (const float*)d_in[4];
    const float* P0   = (const float*)d_in[5];
    float* out = (float*)d_out;

    ekf_k<<<NCH / 32, 32>>>(meas, init, dyna, Q, R, P0);
    dim3 cgrid(TSTEPS / 32, NTRAJ / 32);
    combine_k<<<cgrid, dim3(32, 16)>>>(out);
}

// round 16
// speedup vs baseline: 1.5757x; 1.2330x over previous
#include <cuda_runtime.h>

#define NTRAJ  2048
#define TSTEPS 512
#define KDIM   (TSTEPS * 3)
#define NCH    (3 * NTRAJ)     // 6144 independent 2x2 Kalman chains
#define PF     8
#define DT     0.00833333333333333f

// Paired partials: g_part4[(t>>1)*NCH + chain] = (S_t, M_t, S_{t+1}, M_{t+1}).
__device__ float4 g_part4[(TSTEPS / 2) * NCH];

__device__ __forceinline__ float htanh(float x) {
    float y; asm("tanh.approx.f32 %0, %1;" : "=f"(y) : "f"(x)); return y;
}
__device__ __forceinline__ float frcp(float x) {
    float y; asm("rcp.approx.f32 %0, %1;" : "=f"(y) : "f"(x)); return y;
}

// Deferred-normalization Kalman step: covariance tracked as u = P*d with
// denominator d renormalized to d' = S_true each step. The carried P-loop
// (u -> n00 -> u00') has NO reciprocal on it; rcp(sigma) only feeds the
// state update and the (S, mah) outputs, and its result is recycled as
// next step's invd (d' = sigma*invd, 1/d' = d*invsigma).
struct KState {
    float s0, s1;
    float u00, u01, u11;                 // P * d
    float d, invd, invd2;                // denominator and inverses
    float rd, q0d, q1d, rinvd;           // off-chain per-step products
};

__device__ __forceinline__ void kstep_dn(
    KState& k, float z, float c1, float c2, float c3, float c4,
    float q0, float q1, float r, float& S_out, float& M_out)
{
    float sp = fmaf(DT, k.s1, k.s0);
    float tv = htanh(100.0f * k.s1);
    float vp = fmaf(-c2, tv, c1 * k.s1);
    float a  = fmaf(c3, tv * tv, c4);

    float w   = fmaf(DT, k.u11, k.u01);
    float n00 = fmaf(DT, w, fmaf(DT, k.u01, k.u00)) + k.q0d;
    float n01 = a * w;
    float n11 = fmaf(a * a, k.u11, k.q1d);

    float sig  = n00 + k.rd;             // = S_true * d
    float invs = frcp(sig);
    float S    = __fmul_rn(sig, k.invd); // true S (also next d)
    float yv   = z - sp;
    float K0   = __fmul_rn(n00, invs);   // = n00/sigma = true K0
    float K1   = __fmul_rn(n01, invs);
    k.s0 = fmaf(K0, yv, sp);
    k.s1 = fmaf(K1, yv, vp);

    float dinvs = __fmul_rn(k.d, invs);  // = 1/S (next invd)
    M_out = __fmul_rn(yv * yv, dinvs);
    S_out = S;

    float t1 = fmaf(n11, sig, -(n01 * n01));
    k.u00 = __fmul_rn(k.rinvd, n00);     // = (r*n00/sigma) * d'
    k.u01 = __fmul_rn(k.rinvd, n01);
    k.u11 = __fmul_rn(t1, k.invd2);

    k.d    = S;
    k.invd = dinvs;
    k.rd    = r  * S;
    k.q0d   = q0 * S;
    k.q1d   = q1 * S;
    k.rinvd = r * dinvs;
    k.invd2 = dinvs * dinvs;
}

// 6144 chains, one per lane (192 warps). z read directly from [traj][t][k]
// (12B/step stride -> ~90% L1 hits). Partials: one STG.128 per 2 steps.
__global__ void __launch_bounds__(32, 1) ekf_k(
    const float* __restrict__ meas,
    const float* __restrict__ init_state,
    const float* __restrict__ dyna,
    const float* __restrict__ Q,
    const float* __restrict__ R,
    const float* __restrict__ P0)
{
    const int lane  = threadIdx.x & 31;
    const int chain = blockIdx.x * 32 + lane;
    const int c     = chain >> 11;          // 0,1,2
    const int traj  = chain & (NTRAJ - 1);

    const bool lin = (c == 2);
    const float fric = lin ? 0.0f : __ldg(dyna + 0);
    const float damp = lin ? 0.0f : __ldg(dyna + 1);

    const float c1 = 1.0f - DT * damp;
    const float c2 = DT * fric;
    const float c3 = 100.0f * c2;
    const float c4 = c1 - c3;

    const int pc = lin ? 4 : c;
    const int vc = lin ? 5 : c + 2;

    const float q0 = __ldg(Q + pc * 7);
    const float q1 = __ldg(Q + vc * 7);
    const float r  = __ldg(R + c * 4);

    KState k;
    k.s0 = init_state[traj * 6 + pc];
    k.s1 = init_state[traj * 6 + vc];
    k.u00 = __ldg(P0 + pc * 7);
    k.u01 = __ldg(P0 + pc * 6 + vc);
    k.u11 = __ldg(P0 + vc * 7);
    k.d = 1.0f; k.invd = 1.0f; k.invd2 = 1.0f;
    k.rd = r; k.q0d = q0; k.q1d = q1; k.rinvd = r;

    const float* zb = meas + traj * KDIM + c;   // z(t) at zb[3*t]
    float4*      pp = g_part4 + chain;

    float zr[PF];
    #pragma unroll
    for (int i = 0; i < PF; ++i) zr[i] = zb[3 * i];

    const float* pz = zb + 3 * PF;

    float Sp, Mp;

    // main loop: 504 steps with unconditional prefetch (max step loaded = 511)
    #pragma unroll 1
    for (int t = 0; t < TSTEPS - PF; t += PF) {
        #pragma unroll
        for (int u8 = 0; u8 < PF; ++u8) {
            float z = zr[u8];
            zr[u8] = pz[3 * u8];
            float S, M;
            kstep_dn(k, z, c1, c2, c3, c4, q0, q1, r, S, M);
            if ((u8 & 1) == 0) { Sp = S; Mp = M; }
            else pp[(u8 >> 1) * NCH] = make_float4(Sp, Mp, S, M);
        }
        pz += 3 * PF;
        pp += (PF / 2) * NCH;
    }
    // tail: last 8 steps, no prefetch
    #pragma unroll
    for (int u8 = 0; u8 < PF; ++u8) {
        float S, M;
        kstep_dn(k, zr[u8], c1, c2, c3, c4, q0, q1, r, S, M);
        if ((u8 & 1) == 0) { Sp = S; Mp = M; }
        else pp[(u8 >> 1) * NCH] = make_float4(Sp, Mp, S, M);
    }
}

// loss[traj][t] = (Sx*Sy)*St + (mx+my)+mt from paired partials.
__global__ void combine_k(float* __restrict__ out) {
    __shared__ float tile[32][33];        // [t][traj]
    const int t0  = blockIdx.x * 32;
    const int tr0 = blockIdx.y * 32;
    const int tx = threadIdx.x, ty = threadIdx.y;   // ty in 0..15

    const float4* base = g_part4 + (t0 / 2 + ty) * NCH + tr0 + tx;
    float4 px = base[0];
    float4 py = base[NTRAJ];
    float4 pt = base[2 * NTRAJ];
    tile[2 * ty][tx]     = fmaf(px.x * py.x, pt.x, (px.y + py.y) + pt.y);
    tile[2 * ty + 1][tx] = fmaf(px.z * py.z, pt.z, (px.w + py.w) + pt.w);
    __syncthreads();
    out[(tr0 + ty) * TSTEPS + t0 + tx]      = tile[tx][ty];
    out[(tr0 + ty + 16) * TSTEPS + t0 + tx] = tile[tx][ty + 16];
}

extern "C" void kernel_launch(void* const* d_in, const int* in_sizes, int n_in,
                              void* d_out, int out_size) {
    const float* meas = (const float*)d_in[0];
    const float* init = (const float*)d_in[1];
    const float* dyna = (const float*)d_in[2];
    const float* Q    = (const float*)d_in[3];
    const float* R    = (const float*)d_in[4];
    const float* P0   = (const float*)d_in[5];
    float* out = (float*)d_out;

    ekf_k<<<NCH / 32, 32>>>(meas, init, dyna, Q, R, P0);
    dim3 cgrid(TSTEPS / 32, NTRAJ / 32);
    combine_k<<<cgrid, dim3(32, 16)>>>(out);
}